// round 2
// baseline (speedup 1.0000x reference)
#include <cuda_runtime.h>
#include <math.h>

#define BN 16384
#define KC 64
#define DD 128
#define CH 128
#define NB 8

__device__ int   g_assign[BN];
__device__ int   g_hist[KC];
__device__ int   g_off[KC + 1];
__device__ int   g_counter[KC];
__device__ int   g_sorted[BN];
__device__ float g_mean[KC * DD];
__device__ float g_meanpart[KC];
__device__ float g_covpart[KC];
__device__ float g_cov[KC * DD * DD];

// ---------------- zero scratch ----------------
__global__ void k_zero() {
    int i = blockIdx.x * blockDim.x + threadIdx.x;
    float4* p = (float4*)g_cov;
    if (i < (KC * DD * DD) / 4) p[i] = make_float4(0.f, 0.f, 0.f, 0.f);
    if (i < KC) g_hist[i] = 0;
}

// ---------------- pass A: dist + log_resp + argmin + hist ----------------
// thread handles 2 samples x 16 clusters (quarter q = tid&3), all 128 dims.
__global__ __launch_bounds__(256) void k_passA(const float* __restrict__ x,
                                               const float* __restrict__ cen,
                                               float* __restrict__ out) {
    __shared__ float cs[DD * 68];   // [d][q*17 + kl] skewed layout
    __shared__ float cn2s[KC];
    int tid = threadIdx.x;

    for (int i = tid; i < KC * DD; i += 256) {
        int k = i >> 7;          // centers row
        int d = i & 127;
        cs[d * 68 + (k >> 4) * 17 + (k & 15)] = cen[i];
    }
    if (tid < KC) {
        const float* cr = cen + tid * DD;
        float s0 = 0.f, s1 = 0.f, s2 = 0.f, s3 = 0.f;
        for (int d = 0; d < DD; d += 4) {
            s0 += cr[d] * cr[d];
            s1 += cr[d + 1] * cr[d + 1];
            s2 += cr[d + 2] * cr[d + 2];
            s3 += cr[d + 3] * cr[d + 3];
        }
        cn2s[tid] = (s0 + s1) + (s2 + s3);
    }
    __syncthreads();

    int g = blockIdx.x * 256 + tid;
    int q = g & 3;                 // cluster quarter
    int pairI = g >> 2;            // 0..8191
    int n0 = pairI * 2, n1 = n0 + 1;

    const float4* x40 = (const float4*)(x + (size_t)n0 * DD);
    const float4* x41 = (const float4*)(x + (size_t)n1 * DD);

    float acc0[16], acc1[16];
#pragma unroll
    for (int kl = 0; kl < 16; ++kl) { acc0[kl] = 0.f; acc1[kl] = 0.f; }
    float xn20 = 0.f, xn21 = 0.f;

#pragma unroll 4
    for (int ch = 0; ch < 16; ++ch) {
        float4 a = x40[ch * 2], b = x40[ch * 2 + 1];
        float4 c4 = x41[ch * 2], d4 = x41[ch * 2 + 1];
        float xa[8] = {a.x, a.y, a.z, a.w, b.x, b.y, b.z, b.w};
        float xb[8] = {c4.x, c4.y, c4.z, c4.w, d4.x, d4.y, d4.z, d4.w};
#pragma unroll
        for (int j = 0; j < 8; ++j) {
            xn20 = fmaf(xa[j], xa[j], xn20);
            xn21 = fmaf(xb[j], xb[j], xn21);
        }
        const float* cp = &cs[(ch * 8) * 68 + q * 17];
#pragma unroll
        for (int kl = 0; kl < 16; ++kl) {
#pragma unroll
            for (int j = 0; j < 8; ++j) {
                float cv = cp[j * 68 + kl];
                acc0[kl] = fmaf(xa[j], cv, acc0[kl]);
                acc1[kl] = fmaf(xb[j], cv, acc1[kl]);
            }
        }
    }

    float dist0[16], dist1[16];
    float dmin0 = 3.4e38f, dmin1 = 3.4e38f;
    int km0 = 0, km1 = 0;
#pragma unroll
    for (int kl = 0; kl < 16; ++kl) {
        float cn2 = cn2s[q * 16 + kl];
        float dv0 = fmaf(-2.f, acc0[kl], xn20 + cn2);
        float dv1 = fmaf(-2.f, acc1[kl], xn21 + cn2);
        dist0[kl] = dv0; dist1[kl] = dv1;
        if (dv0 < dmin0) { dmin0 = dv0; km0 = q * 16 + kl; }
        if (dv1 < dmin1) { dmin1 = dv1; km1 = q * 16 + kl; }
    }
    // combine min/argmin across the 4 quarter-lanes (tie -> lowest index)
#pragma unroll
    for (int m = 1; m < 4; m <<= 1) {
        float ov0 = __shfl_xor_sync(0xffffffffu, dmin0, m);
        int   oi0 = __shfl_xor_sync(0xffffffffu, km0, m);
        if (ov0 < dmin0 || (ov0 == dmin0 && oi0 < km0)) { dmin0 = ov0; km0 = oi0; }
        float ov1 = __shfl_xor_sync(0xffffffffu, dmin1, m);
        int   oi1 = __shfl_xor_sync(0xffffffffu, km1, m);
        if (ov1 < dmin1 || (ov1 == dmin1 && oi1 < km1)) { dmin1 = ov1; km1 = oi1; }
    }
    float ls0 = 0.f, ls1 = 0.f;
#pragma unroll
    for (int kl = 0; kl < 16; ++kl) {
        ls0 += __expf(-0.5f * (dist0[kl] - dmin0));
        ls1 += __expf(-0.5f * (dist1[kl] - dmin1));
    }
#pragma unroll
    for (int m = 1; m < 4; m <<= 1) {
        ls0 += __shfl_xor_sync(0xffffffffu, ls0, m);
        ls1 += __shfl_xor_sync(0xffffffffu, ls1, m);
    }
    float lg0 = logf(ls0), lg1 = logf(ls1);
    const float LM = logf(1e-8f);

    float4* o0 = (float4*)(out + (size_t)n0 * KC + q * 16);
    float4* o1 = (float4*)(out + (size_t)n1 * KC + q * 16);
#pragma unroll
    for (int v = 0; v < 4; ++v) {
        float4 r0, r1;
        r0.x = fmaxf(-0.5f * (dist0[4 * v + 0] - dmin0) - lg0, LM);
        r0.y = fmaxf(-0.5f * (dist0[4 * v + 1] - dmin0) - lg0, LM);
        r0.z = fmaxf(-0.5f * (dist0[4 * v + 2] - dmin0) - lg0, LM);
        r0.w = fmaxf(-0.5f * (dist0[4 * v + 3] - dmin0) - lg0, LM);
        r1.x = fmaxf(-0.5f * (dist1[4 * v + 0] - dmin1) - lg1, LM);
        r1.y = fmaxf(-0.5f * (dist1[4 * v + 1] - dmin1) - lg1, LM);
        r1.z = fmaxf(-0.5f * (dist1[4 * v + 2] - dmin1) - lg1, LM);
        r1.w = fmaxf(-0.5f * (dist1[4 * v + 3] - dmin1) - lg1, LM);
        o0[v] = r0; o1[v] = r1;
    }
    if (q == 0) {
        g_assign[n0] = km0;
        g_assign[n1] = km1;
        atomicAdd(&g_hist[km0], 1);
        atomicAdd(&g_hist[km1], 1);
    }
}

// ---------------- pass B: prefix sum ----------------
__global__ void k_passB() {
    if (threadIdx.x == 0) {
        int acc = 0;
        for (int k = 0; k < KC; ++k) {
            g_off[k] = acc;
            g_counter[k] = acc;
            acc += g_hist[k];
        }
        g_off[KC] = acc;
    }
}

// ---------------- pass C: counting-sort scatter ----------------
__global__ void k_passC() {
    int n = blockIdx.x * 256 + threadIdx.x;
    int a = g_assign[n];
    int pos = atomicAdd(&g_counter[a], 1);
    g_sorted[pos] = n;
}

// ---------------- pass D: per-cluster mean + mean_mse partial ----------------
__global__ __launch_bounds__(128) void k_passD(const float* __restrict__ x,
                                               const float* __restrict__ cen) {
    int k = blockIdx.x, t = threadIdx.x;
    int beg = g_off[k], end = g_off[k + 1];
    float s0 = 0.f, s1 = 0.f, s2 = 0.f, s3 = 0.f;
    int i = beg;
    for (; i + 4 <= end; i += 4) {
        int a0 = g_sorted[i], a1 = g_sorted[i + 1], a2 = g_sorted[i + 2], a3 = g_sorted[i + 3];
        s0 += x[(size_t)a0 * DD + t];
        s1 += x[(size_t)a1 * DD + t];
        s2 += x[(size_t)a2 * DD + t];
        s3 += x[(size_t)a3 * DD + t];
    }
    for (; i < end; ++i) s0 += x[(size_t)g_sorted[i] * DD + t];
    float w = (float)(end - beg);
    float m = ((s0 + s1) + (s2 + s3)) / (w + 1e-7f);
    g_mean[k * DD + t] = m;
    float dd = m - cen[k * DD + t];
    dd = dd * dd;
    __shared__ float red[128];
    red[t] = dd;
    __syncthreads();
    for (int s = 64; s > 0; s >>= 1) {
        if (t < s) red[t] += red[t + s];
        __syncthreads();
    }
    if (t == 0) g_meanpart[k] = w * red[0];
}

// ---------------- pass E: per-cluster covariance (chunked SYRK + RED flush) ----------------
__global__ __launch_bounds__(256) void k_passE(const float* __restrict__ x) {
    int tid = threadIdx.x;
    int ti = tid >> 4, tj = tid & 15;
    int ri = ti * 8, cj = tj * 8;
    __shared__ float xs[NB][DD];
    __shared__ float mrow[DD];

    int p0 = blockIdx.x * CH;
    int p1 = min(p0 + CH, BN);

    int k = 0;
    while (k < KC && g_off[k + 1] <= p0) k++;
    for (; k < KC && g_off[k] < p1; ++k) {
        int s0 = max(g_off[k], p0), s1 = min(g_off[k + 1], p1);
        if (s1 <= s0) continue;

        float acc[8][8];
#pragma unroll
        for (int i = 0; i < 8; ++i)
#pragma unroll
            for (int j = 0; j < 8; ++j) acc[i][j] = 0.f;

        __syncthreads();                    // protect mrow vs previous segment readers
        if (tid < DD) mrow[tid] = g_mean[k * DD + tid];

        for (int base = s0; base < s1; base += NB) {
            __syncthreads();                // xs reuse + mrow visibility
#pragma unroll
            for (int u = tid; u < NB * DD; u += 256) {
                int s = u >> 7, d = u & 127;
                int pos = base + s;
                float v = 0.f;
                if (pos < s1) v = x[(size_t)g_sorted[pos] * DD + d] - mrow[d];
                xs[s][d] = v;
            }
            __syncthreads();
#pragma unroll
            for (int s = 0; s < NB; ++s) {
                float rv[8], cv[8];
#pragma unroll
                for (int i = 0; i < 8; ++i) rv[i] = xs[s][ri + i];
#pragma unroll
                for (int j = 0; j < 8; ++j) cv[j] = xs[s][cj + j];
#pragma unroll
                for (int i = 0; i < 8; ++i)
#pragma unroll
                    for (int j = 0; j < 8; ++j) acc[i][j] = fmaf(rv[i], cv[j], acc[i][j]);
            }
        }
        float* cb = g_cov + (size_t)k * DD * DD;
#pragma unroll
        for (int i = 0; i < 8; ++i)
#pragma unroll
            for (int j = 0; j < 8; ++j)
                atomicAdd(&cb[(ri + i) * DD + cj + j], acc[i][j]);
    }
}

// ---------------- pass F1: covar -> per-cluster diag/off terms ----------------
__global__ __launch_bounds__(256) void k_passF1() {
    int k = blockIdx.x, tid = threadIdx.x;
    float w = (float)(g_off[k + 1] - g_off[k]);
    float inv = 1.f / (w + 1e-7f);
    const float* cb = g_cov + (size_t)k * DD * DD;
    float ds = 0.f, os = 0.f;
    for (int i = tid; i < DD * DD; i += 256) {
        float cv = cb[i] * inv;
        int d = i >> 7, e = i & 127;
        if (d == e) { float t = cv - 1.f; ds += t * t; }
        else os += cv * cv;
    }
    __shared__ float rd[256], ro[256];
    rd[tid] = ds; ro[tid] = os;
    __syncthreads();
    for (int s = 128; s > 0; s >>= 1) {
        if (tid < s) { rd[tid] += rd[tid + s]; ro[tid] += ro[tid + s]; }
        __syncthreads();
    }
    if (tid == 0) {
        float bd = (float)BN * (float)DD;
        g_covpart[k] = w * rd[0] / bd + w * ro[0] / (bd * (float)(DD - 1));
    }
}

// ---------------- pass F2: final scalars ----------------
__global__ void k_passF2(float* __restrict__ out_scalars) {
    if (threadIdx.x == 0) {
        float ms = 0.f, cs = 0.f;
        for (int k = 0; k < KC; ++k) { ms += g_meanpart[k]; cs += g_covpart[k]; }
        out_scalars[0] = ms / ((float)BN * (float)DD);
        out_scalars[1] = cs;
    }
}

extern "C" void kernel_launch(void* const* d_in, const int* in_sizes, int n_in,
                              void* d_out, int out_size) {
    const float* x = (const float*)d_in[0];
    const float* c = (const float*)d_in[1];
    float* out = (float*)d_out;

    k_zero<<<1024, 256>>>();
    k_passA<<<128, 256>>>(x, c, out);
    k_passB<<<1, 32>>>();
    k_passC<<<BN / 256, 256>>>();
    k_passD<<<KC, 128>>>(x, c);
    k_passE<<<BN / CH, 256>>>(x);
    k_passF1<<<KC, 256>>>();
    k_passF2<<<1, 32>>>(out + (out_size - 2));
}

// round 3
// speedup vs baseline: 2.0291x; 2.0291x over previous
#include <cuda_runtime.h>
#include <math.h>

#define BN 16384
#define KC 64
#define DD 128
#define CH 128
#define NB 8
#define NBLK_A 256   // passA blocks (64 samples each)

__device__ int   g_assign[BN];
__device__ int   g_bhist[NBLK_A * KC];
__device__ int   g_boff[NBLK_A * KC];
__device__ int   g_off[KC + 1];
__device__ int   g_sorted[BN];
__device__ float g_meansum[KC * DD];
__device__ float g_mean[KC * DD];
__device__ float g_meanpart[KC];
__device__ float g_covpart[KC];
__device__ float g_cov[KC * DD * DD];

// ---------------- zero scratch ----------------
__global__ void k_zero() {
    int i = blockIdx.x * blockDim.x + threadIdx.x;
    float4* p = (float4*)g_cov;
    if (i < (KC * DD * DD) / 4) p[i] = make_float4(0.f, 0.f, 0.f, 0.f);
    if (i < (KC * DD) / 4) ((float4*)g_meansum)[i] = make_float4(0.f, 0.f, 0.f, 0.f);
}

// ---------------- pass A: dist + log_resp + argmin + per-block hist ----------------
// thread handles 2 samples x 8 clusters (octant q = tid&7), all 128 dims.
__global__ __launch_bounds__(256) void k_passA(const float* __restrict__ x,
                                               const float* __restrict__ cen,
                                               float* __restrict__ out) {
    __shared__ float cs[DD * 72];   // [d][q*9 + kl] skewed layout (bank-conflict-free)
    __shared__ float cn2s[KC];
    __shared__ int hist_s[KC];
    int tid = threadIdx.x;

    if (tid < KC) hist_s[tid] = 0;
    for (int i = tid; i < KC * DD; i += 256) {
        int k = i >> 7;          // centers row
        int d = i & 127;
        cs[d * 72 + (k >> 3) * 9 + (k & 7)] = cen[i];
    }
    if (tid < KC) {
        const float* cr = cen + tid * DD;
        float s0 = 0.f, s1 = 0.f, s2 = 0.f, s3 = 0.f;
        for (int d = 0; d < DD; d += 4) {
            s0 += cr[d] * cr[d];
            s1 += cr[d + 1] * cr[d + 1];
            s2 += cr[d + 2] * cr[d + 2];
            s3 += cr[d + 3] * cr[d + 3];
        }
        cn2s[tid] = (s0 + s1) + (s2 + s3);
    }
    __syncthreads();

    int g = blockIdx.x * 256 + tid;
    int q = g & 7;                 // cluster octant
    int pairI = g >> 3;            // 0..8191
    int n0 = pairI * 2, n1 = n0 + 1;

    const float4* x40 = (const float4*)(x + (size_t)n0 * DD);
    const float4* x41 = (const float4*)(x + (size_t)n1 * DD);

    float acc0[8], acc1[8];
#pragma unroll
    for (int kl = 0; kl < 8; ++kl) { acc0[kl] = 0.f; acc1[kl] = 0.f; }
    float xn20 = 0.f, xn21 = 0.f;

#pragma unroll 4
    for (int ch = 0; ch < 16; ++ch) {
        float4 a = x40[ch * 2], b = x40[ch * 2 + 1];
        float4 c4 = x41[ch * 2], d4 = x41[ch * 2 + 1];
        float xa[8] = {a.x, a.y, a.z, a.w, b.x, b.y, b.z, b.w};
        float xb[8] = {c4.x, c4.y, c4.z, c4.w, d4.x, d4.y, d4.z, d4.w};
#pragma unroll
        for (int j = 0; j < 8; ++j) {
            xn20 = fmaf(xa[j], xa[j], xn20);
            xn21 = fmaf(xb[j], xb[j], xn21);
        }
        const float* cp = &cs[(ch * 8) * 72 + q * 9];
#pragma unroll
        for (int kl = 0; kl < 8; ++kl) {
#pragma unroll
            for (int j = 0; j < 8; ++j) {
                float cv = cp[j * 72 + kl];
                acc0[kl] = fmaf(xa[j], cv, acc0[kl]);
                acc1[kl] = fmaf(xb[j], cv, acc1[kl]);
            }
        }
    }

    float dist0[8], dist1[8];
    float dmin0 = 3.4e38f, dmin1 = 3.4e38f;
    int km0 = 0, km1 = 0;
#pragma unroll
    for (int kl = 0; kl < 8; ++kl) {
        float cn2 = cn2s[q * 8 + kl];
        float dv0 = fmaf(-2.f, acc0[kl], xn20 + cn2);
        float dv1 = fmaf(-2.f, acc1[kl], xn21 + cn2);
        dist0[kl] = dv0; dist1[kl] = dv1;
        if (dv0 < dmin0) { dmin0 = dv0; km0 = q * 8 + kl; }
        if (dv1 < dmin1) { dmin1 = dv1; km1 = q * 8 + kl; }
    }
    // combine min/argmin across the 8 octant-lanes (tie -> lowest index)
#pragma unroll
    for (int m = 1; m < 8; m <<= 1) {
        float ov0 = __shfl_xor_sync(0xffffffffu, dmin0, m);
        int   oi0 = __shfl_xor_sync(0xffffffffu, km0, m);
        if (ov0 < dmin0 || (ov0 == dmin0 && oi0 < km0)) { dmin0 = ov0; km0 = oi0; }
        float ov1 = __shfl_xor_sync(0xffffffffu, dmin1, m);
        int   oi1 = __shfl_xor_sync(0xffffffffu, km1, m);
        if (ov1 < dmin1 || (ov1 == dmin1 && oi1 < km1)) { dmin1 = ov1; km1 = oi1; }
    }
    float ls0 = 0.f, ls1 = 0.f;
#pragma unroll
    for (int kl = 0; kl < 8; ++kl) {
        ls0 += __expf(-0.5f * (dist0[kl] - dmin0));
        ls1 += __expf(-0.5f * (dist1[kl] - dmin1));
    }
#pragma unroll
    for (int m = 1; m < 8; m <<= 1) {
        ls0 += __shfl_xor_sync(0xffffffffu, ls0, m);
        ls1 += __shfl_xor_sync(0xffffffffu, ls1, m);
    }
    float lg0 = logf(ls0), lg1 = logf(ls1);
    const float LM = logf(1e-8f);

    float4* o0 = (float4*)(out + (size_t)n0 * KC + q * 8);
    float4* o1 = (float4*)(out + (size_t)n1 * KC + q * 8);
#pragma unroll
    for (int v = 0; v < 2; ++v) {
        float4 r0, r1;
        r0.x = fmaxf(-0.5f * (dist0[4 * v + 0] - dmin0) - lg0, LM);
        r0.y = fmaxf(-0.5f * (dist0[4 * v + 1] - dmin0) - lg0, LM);
        r0.z = fmaxf(-0.5f * (dist0[4 * v + 2] - dmin0) - lg0, LM);
        r0.w = fmaxf(-0.5f * (dist0[4 * v + 3] - dmin0) - lg0, LM);
        r1.x = fmaxf(-0.5f * (dist1[4 * v + 0] - dmin1) - lg1, LM);
        r1.y = fmaxf(-0.5f * (dist1[4 * v + 1] - dmin1) - lg1, LM);
        r1.z = fmaxf(-0.5f * (dist1[4 * v + 2] - dmin1) - lg1, LM);
        r1.w = fmaxf(-0.5f * (dist1[4 * v + 3] - dmin1) - lg1, LM);
        o0[v] = r0; o1[v] = r1;
    }
    if (q == 0) {
        g_assign[n0] = km0;
        g_assign[n1] = km1;
        atomicAdd(&hist_s[km0], 1);
        atomicAdd(&hist_s[km1], 1);
    }
    __syncthreads();
    if (tid < KC) g_bhist[blockIdx.x * KC + tid] = hist_s[tid];
}

// ---------------- pass B: totals + prefix + per-block scatter offsets ----------------
__global__ __launch_bounds__(256) void k_passB() {
    __shared__ int partial[4][KC];
    __shared__ int pre[KC + 1];
    int t = threadIdx.x;
    int k = t & 63, part = t >> 6;
    int s = 0;
    for (int b = part; b < NBLK_A; b += 4) s += g_bhist[b * KC + k];
    partial[part][k] = s;
    __syncthreads();
    if (t == 0) {
        int acc = 0;
        for (int i = 0; i < KC; ++i) {
            pre[i] = acc;
            acc += partial[0][i] + partial[1][i] + partial[2][i] + partial[3][i];
        }
        pre[KC] = acc;
    }
    __syncthreads();
    if (t < KC + 1) g_off[t] = pre[t];
    if (t < KC) {
        int run = pre[t];
        for (int b = 0; b < NBLK_A; ++b) {
            g_boff[b * KC + t] = run;
            run += g_bhist[b * KC + t];
        }
    }
}

// ---------------- pass C: counting-sort scatter (smem-ranked, no global atomics) ----------------
__global__ __launch_bounds__(64) void k_passC() {
    __shared__ int cnt[KC];
    __shared__ int base[KC];
    int t = threadIdx.x, b = blockIdx.x;
    cnt[t] = 0;
    base[t] = g_boff[b * KC + t];
    __syncthreads();
    int n = b * 64 + t;
    int a = g_assign[n];
    int r = atomicAdd(&cnt[a], 1);
    g_sorted[base[a] + r] = n;
}

// ---------------- pass D1: balanced per-segment sum accumulation ----------------
__global__ __launch_bounds__(128) void k_passD1(const float* __restrict__ x) {
    int t = threadIdx.x;
    int p0 = blockIdx.x * 128, p1 = p0 + 128;
    int k = 0;
    while (g_off[k + 1] <= p0) k++;
    int segEnd = g_off[k + 1];
    float acc = 0.f;
    for (int p = p0; p < p1; ++p) {
        while (p >= segEnd) {
            if (acc != 0.f) atomicAdd(&g_meansum[k * DD + t], acc);
            acc = 0.f;
            k++;
            segEnd = g_off[k + 1];
        }
        acc += x[(size_t)g_sorted[p] * DD + t];
    }
    if (acc != 0.f) atomicAdd(&g_meansum[k * DD + t], acc);
}

// ---------------- pass D2: normalize mean + mean_mse partial ----------------
__global__ __launch_bounds__(128) void k_passD2(const float* __restrict__ cen) {
    int k = blockIdx.x, t = threadIdx.x;
    float w = (float)(g_off[k + 1] - g_off[k]);
    float m = g_meansum[k * DD + t] / (w + 1e-7f);
    g_mean[k * DD + t] = m;
    float d = m - cen[k * DD + t];
    d = d * d;
    __shared__ float red[128];
    red[t] = d;
    __syncthreads();
    for (int s = 64; s > 0; s >>= 1) {
        if (t < s) red[t] += red[t + s];
        __syncthreads();
    }
    if (t == 0) g_meanpart[k] = w * red[0];
}

// ---------------- pass E: per-cluster covariance (chunked SYRK + RED flush) ----------------
__global__ __launch_bounds__(256) void k_passE(const float* __restrict__ x) {
    int tid = threadIdx.x;
    int ti = tid >> 4, tj = tid & 15;
    int ri = ti * 8, cj = tj * 8;
    __shared__ float xs[NB][DD];
    __shared__ float mrow[DD];

    int p0 = blockIdx.x * CH;
    int p1 = min(p0 + CH, BN);

    int k = 0;
    while (k < KC && g_off[k + 1] <= p0) k++;
    for (; k < KC && g_off[k] < p1; ++k) {
        int s0 = max(g_off[k], p0), s1 = min(g_off[k + 1], p1);
        if (s1 <= s0) continue;

        float acc[8][8];
#pragma unroll
        for (int i = 0; i < 8; ++i)
#pragma unroll
            for (int j = 0; j < 8; ++j) acc[i][j] = 0.f;

        __syncthreads();                    // protect mrow vs previous segment readers
        if (tid < DD) mrow[tid] = g_mean[k * DD + tid];

        for (int base = s0; base < s1; base += NB) {
            __syncthreads();                // xs reuse + mrow visibility
#pragma unroll
            for (int u = tid; u < NB * DD; u += 256) {
                int s = u >> 7, d = u & 127;
                int pos = base + s;
                float v = 0.f;
                if (pos < s1) v = x[(size_t)g_sorted[pos] * DD + d] - mrow[d];
                xs[s][d] = v;
            }
            __syncthreads();
#pragma unroll
            for (int s = 0; s < NB; ++s) {
                float rv[8], cv[8];
#pragma unroll
                for (int i = 0; i < 8; ++i) rv[i] = xs[s][ri + i];
#pragma unroll
                for (int j = 0; j < 8; ++j) cv[j] = xs[s][cj + j];
#pragma unroll
                for (int i = 0; i < 8; ++i)
#pragma unroll
                    for (int j = 0; j < 8; ++j) acc[i][j] = fmaf(rv[i], cv[j], acc[i][j]);
            }
        }
        float* cb = g_cov + (size_t)k * DD * DD;
#pragma unroll
        for (int i = 0; i < 8; ++i)
#pragma unroll
            for (int j = 0; j < 8; ++j)
                atomicAdd(&cb[(ri + i) * DD + cj + j], acc[i][j]);
    }
}

// ---------------- pass F1: covar -> per-cluster diag/off terms ----------------
__global__ __launch_bounds__(256) void k_passF1() {
    int k = blockIdx.x, tid = threadIdx.x;
    float w = (float)(g_off[k + 1] - g_off[k]);
    float inv = 1.f / (w + 1e-7f);
    const float* cb = g_cov + (size_t)k * DD * DD;
    float ds = 0.f, os = 0.f;
    for (int i = tid; i < DD * DD; i += 256) {
        float cv = cb[i] * inv;
        int d = i >> 7, e = i & 127;
        if (d == e) { float t = cv - 1.f; ds += t * t; }
        else os += cv * cv;
    }
    __shared__ float rd[256], ro[256];
    rd[tid] = ds; ro[tid] = os;
    __syncthreads();
    for (int s = 128; s > 0; s >>= 1) {
        if (tid < s) { rd[tid] += rd[tid + s]; ro[tid] += ro[tid + s]; }
        __syncthreads();
    }
    if (tid == 0) {
        float bd = (float)BN * (float)DD;
        g_covpart[k] = w * rd[0] / bd + w * ro[0] / (bd * (float)(DD - 1));
    }
}

// ---------------- pass F2: final scalars (parallel) ----------------
__global__ __launch_bounds__(64) void k_passF2(float* __restrict__ out_scalars) {
    int t = threadIdx.x;
    float ms = g_meanpart[t], cs = g_covpart[t];
#pragma unroll
    for (int m = 16; m > 0; m >>= 1) {
        ms += __shfl_xor_sync(0xffffffffu, ms, m);
        cs += __shfl_xor_sync(0xffffffffu, cs, m);
    }
    __shared__ float sm[2], sc[2];
    if ((t & 31) == 0) { sm[t >> 5] = ms; sc[t >> 5] = cs; }
    __syncthreads();
    if (t == 0) {
        out_scalars[0] = (sm[0] + sm[1]) / ((float)BN * (float)DD);
        out_scalars[1] = sc[0] + sc[1];
    }
}

extern "C" void kernel_launch(void* const* d_in, const int* in_sizes, int n_in,
                              void* d_out, int out_size) {
    const float* x = (const float*)d_in[0];
    const float* c = (const float*)d_in[1];
    float* out = (float*)d_out;

    k_zero<<<1024, 256>>>();
    k_passA<<<NBLK_A, 256>>>(x, c, out);
    k_passB<<<1, 256>>>();
    k_passC<<<NBLK_A, 64>>>();
    k_passD1<<<BN / 128, 128>>>(x);
    k_passD2<<<KC, 128>>>(c);
    k_passE<<<BN / CH, 256>>>(x);
    k_passF1<<<KC, 256>>>();
    k_passF2<<<1, 64>>>(out + (out_size - 2));
}